// round 8
// baseline (speedup 1.0000x reference)
#include <cuda_runtime.h>

typedef unsigned int u32;
typedef unsigned long long u64;
typedef unsigned char u8;

#define NSEG 2621440u      // voxels per sample == template size (== 2^21 + 2^19)
#define NSAMP 8
#define SEGS 9             // 8 samples + 1 template (template = seg 8 in g_th planes)
#define TPB 256
#define IPT 16
#define TILE 4096          // TPB*IPT
#define TILES 640          // NSEG / TILE (exact)
#define IDXMASK 0x3FFFFFu  // 22 bits; NSEG < 2^22

// Static device scratch
__device__ u64 g_bufA[(size_t)NSAMP * NSEG];     // sample u64 records (passes 0-1); aliased as u32 recs after pass 2
__device__ u64 g_bufB[(size_t)NSAMP * NSEG];
__device__ u32 g_tmplA[NSEG];                    // template keys-only buffers
__device__ u32 g_tmplB[NSEG];
__device__ u32 g_th[4ull * SEGS * 256 * TILES];  // per (pass,seg,digit,tile) counts -> abs offsets
__device__ u32 g_ghist[4 * SEGS * 256];
__device__ u32 g_gbase[4 * SEGS * 256];
__device__ float g_tval[NSEG];                   // sorted template values

__device__ __forceinline__ u32 f2k(float f) {
    u32 u = __float_as_uint(f);
    return u ^ ((u & 0x80000000u) ? 0xFFFFFFFFu : 0x80000000u);
}
__device__ __forceinline__ float k2f(u32 u) {
    u ^= ((u & 0x80000000u) ? 0x80000000u : 0xFFFFFFFFu);
    return __uint_as_float(u);
}

// ---------------- zero global hists ----------------
__global__ void zero_k() {
    u32 i = blockIdx.x * blockDim.x + threadIdx.x;
    if (i < 4 * SEGS * 256) g_ghist[i] = 0;
}

// ---------------- hist0: read floats, global 4-plane hist + pass-0 per-tile hist ----------------
__global__ void __launch_bounds__(TPB) hist0_k(const float* __restrict__ x,
                                               const float* __restrict__ t) {
    __shared__ u32 h[4][256];
    const int tid = threadIdx.x;
    const int l = tid & 31;
    const int seg = blockIdx.y;          // 0..8
    const int tile = blockIdx.x;
    for (int i = tid; i < 4 * 256; i += TPB) (&h[0][0])[i] = 0;
    __syncthreads();

    const float* src = (seg < NSAMP) ? (x + (size_t)seg * NSEG) : t;
    const u32 base = tile * TILE;
    #pragma unroll
    for (int k = 0; k < 4; k++) {
        u32 j = base + (u32)(k * TPB * 4) + tid * 4;
        float4 v = *reinterpret_cast<const float4*>(src + j);
        u32 kk[4] = { f2k(v.x), f2k(v.y), f2k(v.z), f2k(v.w) };
        #pragma unroll
        for (int e = 0; e < 4; e++) {
            atomicAdd(&h[0][kk[e] & 255u], 1u);
            atomicAdd(&h[1][(kk[e] >> 8) & 255u], 1u);
            u32 d2 = (kk[e] >> 16) & 255u;
            u32 m2 = __match_any_sync(0xFFFFFFFFu, d2);
            if ((int)(__ffs(m2) - 1) == l) atomicAdd(&h[2][d2], (u32)__popc(m2));
            u32 d3 = kk[e] >> 24;
            u32 m3 = __match_any_sync(0xFFFFFFFFu, d3);
            if ((int)(__ffs(m3) - 1) == l) atomicAdd(&h[3][d3], (u32)__popc(m3));
        }
    }
    __syncthreads();
    #pragma unroll
    for (int p = 0; p < 4; p++) {
        u32 c = h[p][tid];
        if (c) atomicAdd(&g_ghist[(p * SEGS + seg) * 256 + tid], c);
    }
    g_th[((size_t)(0 * SEGS + seg) * 256 + tid) * TILES + tile] = h[0][tid];
}

// ---------------- per-tile hist over u64 records (key = high u32) ----------------
template<int SHIFT>
__global__ void __launch_bounds__(TPB) hist_u64_k(const u64* __restrict__ src, int plane) {
    __shared__ u32 h[8][256];
    const u32* __restrict__ in = reinterpret_cast<const u32*>(src);
    const int t = threadIdx.x;
    const int w = t >> 5;
    const int l = t & 31;
    const int tile = blockIdx.x, seg = blockIdx.y;
    #pragma unroll
    for (int i = t; i < 8 * 256; i += TPB) (&h[0][0])[i] = 0;
    __syncthreads();
    const size_t base = 2 * ((size_t)seg * NSEG + (size_t)tile * TILE) + 1;
    #pragma unroll
    for (int k = 0; k < IPT; k++) {
        u32 key = __ldcs(&in[base + 2 * (size_t)(k * TPB + t)]);
        u32 d = (key >> SHIFT) & 255u;
        if (SHIFT >= 16) {
            u32 m = __match_any_sync(0xFFFFFFFFu, d);
            if ((int)(__ffs(m) - 1) == l) atomicAdd(&h[w][d], (u32)__popc(m));
        } else {
            atomicAdd(&h[w][d], 1u);
        }
    }
    __syncthreads();
    u32 s = 0;
    #pragma unroll
    for (int w2 = 0; w2 < 8; w2++) s += h[w2][t];
    g_th[((size_t)(plane * SEGS + seg) * 256 + t) * TILES + tile] = s;
}

// ---------------- per-tile hist over u32 records ----------------
template<int SHIFT>
__global__ void __launch_bounds__(TPB) hist_u32_k(const u32* __restrict__ src,
                                                  int plane, int segOff) {
    __shared__ u32 h[8][256];
    const uint4* __restrict__ in4 = reinterpret_cast<const uint4*>(src);
    const int t = threadIdx.x;
    const int w = t >> 5;
    const int l = t & 31;
    const int tile = blockIdx.x;
    const int segG = blockIdx.y + segOff;
    #pragma unroll
    for (int i = t; i < 8 * 256; i += TPB) (&h[0][0])[i] = 0;
    __syncthreads();
    const size_t base4 = ((size_t)blockIdx.y * NSEG + (size_t)tile * TILE) >> 2;
    #pragma unroll
    for (int k = 0; k < 4; k++) {
        uint4 q = __ldcs(&in4[base4 + (size_t)k * TPB + t]);
        u32 dd[4] = { (q.x >> SHIFT) & 255u, (q.y >> SHIFT) & 255u,
                      (q.z >> SHIFT) & 255u, (q.w >> SHIFT) & 255u };
        #pragma unroll
        for (int e = 0; e < 4; e++) {
            if (SHIFT > 8) {   // skewed digits: warp-aggregate
                u32 m = __match_any_sync(0xFFFFFFFFu, dd[e]);
                if ((int)(__ffs(m) - 1) == l) atomicAdd(&h[w][dd[e]], (u32)__popc(m));
            } else {
                atomicAdd(&h[w][dd[e]], 1u);
            }
        }
    }
    __syncthreads();
    u32 s = 0;
    #pragma unroll
    for (int w2 = 0; w2 < 8; w2++) s += h[w2][t];
    g_th[((size_t)(plane * SEGS + segG) * 256 + t) * TILES + tile] = s;
}

// ---------------- per-(pass,seg) exclusive digit scan ----------------
__global__ void gscan_k() {
    __shared__ u32 wsum[8];
    const int seg = blockIdx.x, p = blockIdx.y;
    const int t = threadIdx.x, l = t & 31, w = t >> 5;
    u32 tot = g_ghist[(p * SEGS + seg) * 256 + t];
    u32 v = tot;
    #pragma unroll
    for (int off = 1; off < 32; off <<= 1) {
        u32 n = __shfl_up_sync(0xFFFFFFFFu, v, off);
        if (l >= off) v += n;
    }
    if (l == 31) wsum[w] = v;
    __syncthreads();
    if (t == 0) {
        u32 run = 0;
        #pragma unroll
        for (int i = 0; i < 8; i++) { u32 c = wsum[i]; wsum[i] = run; run += c; }
    }
    __syncthreads();
    g_gbase[(p * SEGS + seg) * 256 + t] = wsum[w] + v - tot;
}

// ---------------- per-(seg,digit) scan over tiles ----------------
__global__ void __launch_bounds__(256) tscan_k(int P) {
    const int seg = blockIdx.x;
    const int t = threadIdx.x, w = t >> 5, l = t & 31;
    const int d = blockIdx.y * 8 + w;
    u32* row = g_th + ((size_t)(P * SEGS + seg) * 256 + d) * TILES;
    u32 run = g_gbase[(P * SEGS + seg) * 256 + d];
    for (int c = 0; c < TILES; c += 32) {
        u32 v = row[c + l];
        u32 s = v;
        #pragma unroll
        for (int off = 1; off < 32; off <<= 1) {
            u32 n = __shfl_up_sync(0xFFFFFFFFu, s, off);
            if (l >= off) s += n;
        }
        row[c + l] = run + s - v;
        run += __shfl_sync(0xFFFFFFFFu, s, 31);
    }
}

// ---------------- generic stable rank + direct scatter (R5 engine) ----------------
// SRC: 0 = float input (key=f2k, payload=index), 1 = u64 records (key hi32, payload lo32),
//      2 = u32 records (key = record)
// OUT: 0 = u64 (key<<32|payload), 1 = u32 key, 2 = u32 rec ((key>>24)<<22|idx),
//      3 = g_tval[pos]=k2f(key), 4 = out[idx] = g_tval[pos]
template<int SRC, int SHIFT, int OUT>
__global__ void __launch_bounds__(TPB) scat_k(const void* __restrict__ srcv,
                                              void* __restrict__ dstv,
                                              float* __restrict__ outf,
                                              int plane, int segOff) {
    __shared__ u8 cnt8[IPT * 8 * 256];   // 32 KB
    __shared__ u32 rb[IPT * 256];        // 16 KB

    const int t = threadIdx.x;
    const int w = t >> 5;
    const int l = t & 31;
    const u32 lmlt = (1u << l) - 1u;
    const u32 tile = blockIdx.x;
    const int segG = blockIdx.y + segOff;              // index into g_th planes
    const size_t srcOff = (size_t)blockIdx.y * NSEG + (size_t)tile * TILE;
    const size_t dstOff = (size_t)blockIdx.y * NSEG;

    // load items
    u32 keyv[IPT];
    u32 payv[IPT];
    if (SRC == 0) {
        const float* src = (const float*)srcv;
        #pragma unroll
        for (int k = 0; k < IPT; k++) {
            float v = __ldcs(&src[srcOff + (size_t)k * TPB + t]);
            keyv[k] = f2k(v);
            payv[k] = tile * TILE + (u32)(k * TPB) + t;   // index within segment
        }
    } else if (SRC == 1) {
        const u64* src = (const u64*)srcv;
        #pragma unroll
        for (int k = 0; k < IPT; k++) {
            u64 it = __ldcs(&src[srcOff + (size_t)k * TPB + t]);
            keyv[k] = (u32)(it >> 32);
            payv[k] = (u32)it;
        }
    } else {
        const u32* src = (const u32*)srcv;
        #pragma unroll
        for (int k = 0; k < IPT; k++) {
            keyv[k] = __ldcs(&src[srcOff + (size_t)k * TPB + t]);
            payv[k] = 0;
        }
    }

    // absolute digit base for (segG, digit t, tile)
    u32 run = g_th[((size_t)(plane * SEGS + segG) * 256 + t) * TILES + tile];

    // zero counters
    u32* c32 = reinterpret_cast<u32*>(cnt8);
    #pragma unroll
    for (int i = 0; i < (IPT * 8 * 256 / 4) / TPB; i++) c32[i * TPB + t] = 0;
    __syncthreads();

    // warp match ranking; leaders record per-(round,warp,digit) counts
    u32 lr0 = 0, lr1 = 0, lr2 = 0, lr3 = 0;
    #pragma unroll
    for (int k = 0; k < IPT; k++) {
        u32 d = (keyv[k] >> SHIFT) & 255u;
        u32 m = __match_any_sync(0xFFFFFFFFu, d);
        u32 r = __popc(m & lmlt);
        if (r == 0) cnt8[(k * 8 + w) * 256 + d] = (u8)__popc(m);
        if (k < 4)       lr0 |= r << (8 * k);
        else if (k < 8)  lr1 |= r << (8 * (k - 4));
        else if (k < 12) lr2 |= r << (8 * (k - 8));
        else             lr3 |= r << (8 * (k - 12));
    }
    __syncthreads();

    // thread t owns digit t; serial prefix over 128 (round, warp) cells
    #pragma unroll
    for (int k = 0; k < IPT; k++) {
        rb[k * 256 + t] = run;
        u32 rs = run;
        #pragma unroll
        for (int w2 = 0; w2 < 8; w2++) {
            u32 i = (u32)(k * 8 + w2) * 256 + t;
            u32 c = cnt8[i];
            cnt8[i] = (u8)(run - rs);
            run += c;
        }
    }
    __syncthreads();

    // final positions, direct global write
    #pragma unroll
    for (int k = 0; k < IPT; k++) {
        u32 d = (keyv[k] >> SHIFT) & 255u;
        u32 r;
        if (k < 4)       r = (lr0 >> (8 * k)) & 255u;
        else if (k < 8)  r = (lr1 >> (8 * (k - 4))) & 255u;
        else if (k < 12) r = (lr2 >> (8 * (k - 8))) & 255u;
        else             r = (lr3 >> (8 * (k - 12))) & 255u;
        u32 pos = rb[k * 256 + d] + (u32)cnt8[(k * 8 + w) * 256 + d] + r;
        if (OUT == 0) {
            ((u64*)dstv)[dstOff + pos] = ((u64)keyv[k] << 32) | payv[k];
        } else if (OUT == 1) {
            ((u32*)dstv)[dstOff + pos] = keyv[k];
        } else if (OUT == 2) {
            ((u32*)dstv)[dstOff + pos] = ((keyv[k] >> 24) << 22) | (payv[k] & IDXMASK);
        } else if (OUT == 3) {
            g_tval[pos] = k2f(keyv[k]);
        } else {
            outf[(size_t)blockIdx.y * NSEG + (keyv[k] & IDXMASK)] = __ldg(&g_tval[pos]);
        }
    }
}

extern "C" void kernel_launch(void* const* d_in, const int* in_sizes, int n_in,
                              void* d_out, int out_size) {
    const float* x  = (const float*)d_in[0];
    const float* bv = (const float*)d_in[1];
    float* out = (float*)d_out;

    u32* recs = (u32*)g_bufA;   // pass-2 output aliases bufA as u32 records

    dim3 gS(TILES, NSAMP), gT(TILES, 1);

    zero_k<<<36, 256>>>();
    hist0_k<<<dim3(TILES, SEGS), TPB>>>(x, bv);
    gscan_k<<<dim3(SEGS, 4), 256>>>();

    // ---- pass 0: floats -> records (fused pack) ----
    tscan_k<<<dim3(SEGS, 32), 256>>>(0);
    scat_k<0, 0, 0><<<gS, TPB>>>(x,  g_bufA,  nullptr, 0, 0);      // samples: x -> A (u64)
    scat_k<0, 0, 1><<<gT, TPB>>>(bv, g_tmplA, nullptr, 0, NSAMP);  // template: bv -> tA (u32 keys)

    // ---- pass 1 ----
    hist_u64_k<8><<<gS, TPB>>>(g_bufA, 1);
    hist_u32_k<8><<<gT, TPB>>>(g_tmplA, 1, NSAMP);
    tscan_k<<<dim3(SEGS, 32), 256>>>(1);
    scat_k<1, 8, 0><<<gS, TPB>>>(g_bufA,  g_bufB,  nullptr, 1, 0);     // A -> B
    scat_k<2, 8, 1><<<gT, TPB>>>(g_tmplA, g_tmplB, nullptr, 1, NSAMP); // tA -> tB

    // ---- pass 2 (samples compress to u32 records) ----
    hist_u64_k<16><<<gS, TPB>>>(g_bufB, 2);
    hist_u32_k<16><<<gT, TPB>>>(g_tmplB, 2, NSAMP);
    tscan_k<<<dim3(SEGS, 32), 256>>>(2);
    scat_k<1, 16, 2><<<gS, TPB>>>(g_bufB,  recs,    nullptr, 2, 0);     // B -> recs (u32)
    scat_k<2, 16, 1><<<gT, TPB>>>(g_tmplB, g_tmplA, nullptr, 2, NSAMP); // tB -> tA

    // ---- pass 3 ----
    hist_u32_k<22><<<gS, TPB>>>(recs, 3, 0);        // rec digit = byte3 of key
    hist_u32_k<24><<<gT, TPB>>>(g_tmplA, 3, NSAMP); // template key byte3
    tscan_k<<<dim3(SEGS, 32), 256>>>(3);
    scat_k<2, 24, 3><<<gT, TPB>>>(g_tmplA, nullptr, nullptr, 3, NSAMP); // tA -> g_tval
    scat_k<2, 22, 4><<<gS, TPB>>>(recs, nullptr, out, 3, 0);            // fused epilogue
}

// round 9
// speedup vs baseline: 27.4556x; 27.4556x over previous
#include <cuda_runtime.h>

typedef unsigned int u32;
typedef unsigned long long u64;
typedef unsigned char u8;

#define NSEG 2621440u      // voxels per sample == template size
#define NSAMP 8
#define SEGS 9             // 8 samples + 1 template
#define TPB 256
#define IPT 16
#define TILE 4096          // TPB*IPT
#define TILES 640          // NSEG / TILE (exact)
#define IDXMASK 0x3FFFFFu  // 22 bits

// Static device scratch
__device__ u64 g_bufA[(size_t)SEGS * NSEG];
__device__ u64 g_bufB[(size_t)SEGS * NSEG];   // samples' pass-2 u32 recs alias its low half
__device__ u32 g_th[4ull * SEGS * 256 * TILES];  // per (pass,seg,digit,tile) counts -> abs offsets
__device__ u32 g_ghist[4 * SEGS * 256];          // global digit hist per (pass,seg)
__device__ u32 g_gbase[4 * SEGS * 256];          // exclusive scan of g_ghist
__device__ float g_tval[NSEG];                   // sorted template values

__device__ __forceinline__ u32 f2k(float f) {
    u32 u = __float_as_uint(f);
    return u ^ ((u & 0x80000000u) ? 0xFFFFFFFFu : 0x80000000u);
}
__device__ __forceinline__ float k2f(u32 u) {
    u ^= ((u & 0x80000000u) ? 0x80000000u : 0xFFFFFFFFu);
    return __uint_as_float(u);
}

// ---------------- zero global hists ----------------
__global__ void zero_k() {
    u32 i = blockIdx.x * blockDim.x + threadIdx.x;
    if (i < 4 * SEGS * 256) g_ghist[i] = 0;
}

// ---------------- fused pack + global 4-plane hist + pass-0 per-tile hist ----------------
__global__ void __launch_bounds__(TPB) pack_hist_k(const float* __restrict__ x,
                                                   const float* __restrict__ t) {
    __shared__ u32 h[4][256];
    const int tid = threadIdx.x;
    const int l = tid & 31;
    const int seg = blockIdx.y;
    const int tile = blockIdx.x;
    for (int i = tid; i < 4 * 256; i += TPB) (&h[0][0])[i] = 0;
    __syncthreads();

    const float* src = (seg < NSAMP) ? (x + (size_t)seg * NSEG) : t;
    u64* dst = g_bufA + (size_t)seg * NSEG;
    const u32 base = tile * TILE;
    #pragma unroll
    for (int k = 0; k < 4; k++) {
        u32 j = base + (u32)(k * TPB * 4) + tid * 4;
        float4 v = *reinterpret_cast<const float4*>(src + j);
        u32 kk[4] = { f2k(v.x), f2k(v.y), f2k(v.z), f2k(v.w) };
        #pragma unroll
        for (int e = 0; e < 4; e++) {
            dst[j + e] = ((u64)kk[e] << 32) | (j + e);
            atomicAdd(&h[0][kk[e] & 255u], 1u);
            atomicAdd(&h[1][(kk[e] >> 8) & 255u], 1u);
            u32 d2 = (kk[e] >> 16) & 255u;
            u32 m2 = __match_any_sync(0xFFFFFFFFu, d2);
            if ((int)(__ffs(m2) - 1) == l) atomicAdd(&h[2][d2], (u32)__popc(m2));
            u32 d3 = kk[e] >> 24;
            u32 m3 = __match_any_sync(0xFFFFFFFFu, d3);
            if ((int)(__ffs(m3) - 1) == l) atomicAdd(&h[3][d3], (u32)__popc(m3));
        }
    }
    __syncthreads();
    #pragma unroll
    for (int p = 0; p < 4; p++) {
        u32 c = h[p][tid];
        if (c) atomicAdd(&g_ghist[(p * SEGS + seg) * 256 + tid], c);
    }
    g_th[((size_t)(0 * SEGS + seg) * 256 + tid) * TILES + tile] = h[0][tid];
}

// ---------------- per-tile hist over u64 items (key u32) for passes 1..3 ----------------
template<int PASS>
__global__ void __launch_bounds__(TPB) hist_k(int segOff) {
    __shared__ u32 h[8][256];
    const u32* __restrict__ in = reinterpret_cast<const u32*>((PASS & 1) ? g_bufB : g_bufA);
    const int t = threadIdx.x;
    const int w = t >> 5;
    const int tile = blockIdx.x, seg = blockIdx.y + segOff;
    #pragma unroll
    for (int i = t; i < 8 * 256; i += TPB) (&h[0][0])[i] = 0;
    __syncthreads();
    const size_t base = 2 * ((size_t)seg * NSEG + (size_t)tile * TILE) + 1;
    #pragma unroll
    for (int k = 0; k < IPT; k++) {
        u32 key = __ldcs(&in[base + 2 * (size_t)(k * TPB + t)]);
        atomicAdd(&h[w][(key >> (8 * PASS)) & 255u], 1u);
    }
    __syncthreads();
    u32 s = 0;
    #pragma unroll
    for (int w2 = 0; w2 < 8; w2++) s += h[w2][t];
    g_th[((size_t)(PASS * SEGS + seg) * 256 + t) * TILES + tile] = s;
}

// ---------------- per-tile hist over u32 recs (pass 3, samples): digit = bits[22:30) ----------------
__global__ void __launch_bounds__(TPB) hist_rec_k() {
    __shared__ u32 h[8][256];
    const uint4* __restrict__ in4 = reinterpret_cast<const uint4*>(g_bufB);
    const int t = threadIdx.x;
    const int w = t >> 5;
    const int l = t & 31;
    const int tile = blockIdx.x, seg = blockIdx.y;
    #pragma unroll
    for (int i = t; i < 8 * 256; i += TPB) (&h[0][0])[i] = 0;
    __syncthreads();
    const size_t base4 = ((size_t)seg * NSEG + (size_t)tile * TILE) >> 2;
    #pragma unroll
    for (int k = 0; k < 4; k++) {
        uint4 q = __ldcs(&in4[base4 + (size_t)k * TPB + t]);
        u32 dd[4] = { (q.x >> 22) & 255u, (q.y >> 22) & 255u,
                      (q.z >> 22) & 255u, (q.w >> 22) & 255u };
        #pragma unroll
        for (int e = 0; e < 4; e++) {   // byte3 digits are skewed: warp-aggregate
            u32 m = __match_any_sync(0xFFFFFFFFu, dd[e]);
            if ((int)(__ffs(m) - 1) == l) atomicAdd(&h[w][dd[e]], (u32)__popc(m));
        }
    }
    __syncthreads();
    u32 s = 0;
    #pragma unroll
    for (int w2 = 0; w2 < 8; w2++) s += h[w2][t];
    g_th[((size_t)(3 * SEGS + seg) * 256 + t) * TILES + tile] = s;
}

// ---------------- per-(pass,seg) exclusive digit scan ----------------
__global__ void gscan_k() {
    __shared__ u32 wsum[8];
    const int seg = blockIdx.x, p = blockIdx.y;
    const int t = threadIdx.x, l = t & 31, w = t >> 5;
    u32 tot = g_ghist[(p * SEGS + seg) * 256 + t];
    u32 v = tot;
    #pragma unroll
    for (int off = 1; off < 32; off <<= 1) {
        u32 n = __shfl_up_sync(0xFFFFFFFFu, v, off);
        if (l >= off) v += n;
    }
    if (l == 31) wsum[w] = v;
    __syncthreads();
    if (t == 0) {
        u32 run = 0;
        #pragma unroll
        for (int i = 0; i < 8; i++) { u32 c = wsum[i]; wsum[i] = run; run += c; }
    }
    __syncthreads();
    g_gbase[(p * SEGS + seg) * 256 + t] = wsum[w] + v - tot;
}

// ---------------- per-(seg,digit) scan over tiles ----------------
__global__ void __launch_bounds__(256) tscan_k(int P) {
    const int seg = blockIdx.x;
    const int t = threadIdx.x, w = t >> 5, l = t & 31;
    const int d = blockIdx.y * 8 + w;
    u32* row = g_th + ((size_t)(P * SEGS + seg) * 256 + d) * TILES;
    u32 run = g_gbase[(P * SEGS + seg) * 256 + d];
    for (int c = 0; c < TILES; c += 32) {
        u32 v = row[c + l];
        u32 s = v;
        #pragma unroll
        for (int off = 1; off < 32; off <<= 1) {
            u32 n = __shfl_up_sync(0xFFFFFFFFu, s, off);
            if (l >= off) s += n;
        }
        row[c + l] = run + s - v;
        run += __shfl_sync(0xFFFFFFFFu, s, 31);
    }
}

// ---------------- stable rank + direct scatter (R5 engine, u64 items) ----------------
// MODE 0: sorted u64 items -> other buffer
// MODE 2: g_tval[pos] = key-as-float                 (template, pass 3)
// MODE 3: u32 rec (byte3<<22)|idx -> other buffer    (samples, pass 2)
template<int PASS, int MODE>
__global__ void __launch_bounds__(TPB) scatter_k(int segOff) {
    __shared__ u8 cnt8[IPT * 8 * 256];   // 32 KB
    __shared__ u32 rb[IPT * 256];        // 16 KB

    const int t = threadIdx.x;
    const int w = t >> 5;
    const int l = t & 31;
    const u32 lmlt = (1u << l) - 1u;
    const u32 tile = blockIdx.x;
    const int seg = blockIdx.y + segOff;
    constexpr int SHIFT = 32 + 8 * PASS;

    const u64* __restrict__ in = (PASS & 1) ? g_bufB : g_bufA;
    u64* __restrict__ outp     = (PASS & 1) ? g_bufA : g_bufB;
    const size_t sbase = (size_t)seg * NSEG;
    const size_t base = sbase + (size_t)tile * TILE;

    u64 item[IPT];
    #pragma unroll
    for (int k = 0; k < IPT; k++) item[k] = __ldcs(&in[base + (size_t)k * TPB + t]);

    u32 run = g_th[((size_t)(PASS * SEGS + seg) * 256 + t) * TILES + tile];

    u32* c32 = reinterpret_cast<u32*>(cnt8);
    #pragma unroll
    for (int i = 0; i < (IPT * 8 * 256 / 4) / TPB; i++) c32[i * TPB + t] = 0;
    __syncthreads();

    u32 lr0 = 0, lr1 = 0, lr2 = 0, lr3 = 0;
    #pragma unroll
    for (int k = 0; k < IPT; k++) {
        u32 d = (u32)(item[k] >> SHIFT) & 255u;
        u32 m = __match_any_sync(0xFFFFFFFFu, d);
        u32 r = __popc(m & lmlt);
        if (r == 0) cnt8[(k * 8 + w) * 256 + d] = (u8)__popc(m);
        if (k < 4)       lr0 |= r << (8 * k);
        else if (k < 8)  lr1 |= r << (8 * (k - 4));
        else if (k < 12) lr2 |= r << (8 * (k - 8));
        else             lr3 |= r << (8 * (k - 12));
    }
    __syncthreads();

    #pragma unroll
    for (int k = 0; k < IPT; k++) {
        rb[k * 256 + t] = run;
        u32 rs = run;
        #pragma unroll
        for (int w2 = 0; w2 < 8; w2++) {
            u32 i = (u32)(k * 8 + w2) * 256 + t;
            u32 c = cnt8[i];
            cnt8[i] = (u8)(run - rs);
            run += c;
        }
    }
    __syncthreads();

    #pragma unroll
    for (int k = 0; k < IPT; k++) {
        u32 d = (u32)(item[k] >> SHIFT) & 255u;
        u32 r;
        if (k < 4)       r = (lr0 >> (8 * k)) & 255u;
        else if (k < 8)  r = (lr1 >> (8 * (k - 4))) & 255u;
        else if (k < 12) r = (lr2 >> (8 * (k - 8))) & 255u;
        else             r = (lr3 >> (8 * (k - 12))) & 255u;
        u32 pos = rb[k * 256 + d] + (u32)cnt8[(k * 8 + w) * 256 + d] + r;
        if (MODE == 0) {
            outp[sbase + pos] = item[k];
        } else if (MODE == 2) {
            g_tval[pos] = k2f((u32)(item[k] >> 32));
        } else {  // MODE 3: compress to u32 rec
            reinterpret_cast<u32*>(outp)[sbase + pos] =
                ((u32)(item[k] >> 56) << 22) | ((u32)item[k] & IDXMASK);
        }
    }
}

// ---------------- pass-3 epilogue over u32 recs: out[idx] = g_tval[pos] ----------------
__global__ void __launch_bounds__(TPB) scatter_rec_k(float* __restrict__ outf) {
    __shared__ u8 cnt8[IPT * 8 * 256];
    __shared__ u32 rb[IPT * 256];

    const int t = threadIdx.x;
    const int w = t >> 5;
    const int l = t & 31;
    const u32 lmlt = (1u << l) - 1u;
    const u32 tile = blockIdx.x;
    const int seg = blockIdx.y;
    const u32* __restrict__ in = reinterpret_cast<const u32*>(g_bufB);
    const size_t sbase = (size_t)seg * NSEG;
    const size_t base = sbase + (size_t)tile * TILE;

    u32 rec[IPT];
    #pragma unroll
    for (int k = 0; k < IPT; k++) rec[k] = __ldcs(&in[base + (size_t)k * TPB + t]);

    u32 run = g_th[((size_t)(3 * SEGS + seg) * 256 + t) * TILES + tile];

    u32* c32 = reinterpret_cast<u32*>(cnt8);
    #pragma unroll
    for (int i = 0; i < (IPT * 8 * 256 / 4) / TPB; i++) c32[i * TPB + t] = 0;
    __syncthreads();

    u32 lr0 = 0, lr1 = 0, lr2 = 0, lr3 = 0;
    #pragma unroll
    for (int k = 0; k < IPT; k++) {
        u32 d = (rec[k] >> 22) & 255u;
        u32 m = __match_any_sync(0xFFFFFFFFu, d);
        u32 r = __popc(m & lmlt);
        if (r == 0) cnt8[(k * 8 + w) * 256 + d] = (u8)__popc(m);
        if (k < 4)       lr0 |= r << (8 * k);
        else if (k < 8)  lr1 |= r << (8 * (k - 4));
        else if (k < 12) lr2 |= r << (8 * (k - 8));
        else             lr3 |= r << (8 * (k - 12));
    }
    __syncthreads();

    #pragma unroll
    for (int k = 0; k < IPT; k++) {
        rb[k * 256 + t] = run;
        u32 rs = run;
        #pragma unroll
        for (int w2 = 0; w2 < 8; w2++) {
            u32 i = (u32)(k * 8 + w2) * 256 + t;
            u32 c = cnt8[i];
            cnt8[i] = (u8)(run - rs);
            run += c;
        }
    }
    __syncthreads();

    #pragma unroll
    for (int k = 0; k < IPT; k++) {
        u32 d = (rec[k] >> 22) & 255u;
        u32 r;
        if (k < 4)       r = (lr0 >> (8 * k)) & 255u;
        else if (k < 8)  r = (lr1 >> (8 * (k - 4))) & 255u;
        else if (k < 12) r = (lr2 >> (8 * (k - 8))) & 255u;
        else             r = (lr3 >> (8 * (k - 12))) & 255u;
        u32 pos = rb[k * 256 + d] + (u32)cnt8[(k * 8 + w) * 256 + d] + r;
        outf[sbase + (rec[k] & IDXMASK)] = __ldg(&g_tval[pos]);
    }
}

extern "C" void kernel_launch(void* const* d_in, const int* in_sizes, int n_in,
                              void* d_out, int out_size) {
    const float* x  = (const float*)d_in[0];
    const float* bv = (const float*)d_in[1];
    float* out = (float*)d_out;

    zero_k<<<36, 256>>>();
    pack_hist_k<<<dim3(TILES, SEGS), TPB>>>(x, bv);
    gscan_k<<<dim3(SEGS, 4), 256>>>();

    tscan_k<<<dim3(SEGS, 32), 256>>>(0);
    scatter_k<0, 0><<<dim3(TILES, SEGS), TPB>>>(0);           // A -> B (u64)

    hist_k<1><<<dim3(TILES, SEGS), TPB>>>(0);
    tscan_k<<<dim3(SEGS, 32), 256>>>(1);
    scatter_k<1, 0><<<dim3(TILES, SEGS), TPB>>>(0);           // B -> A (u64)

    hist_k<2><<<dim3(TILES, SEGS), TPB>>>(0);
    tscan_k<<<dim3(SEGS, 32), 256>>>(2);
    scatter_k<2, 3><<<dim3(TILES, NSAMP), TPB>>>(0);          // samples: A -> u32 recs (in B's low half)
    scatter_k<2, 0><<<dim3(TILES, 1), TPB>>>(NSAMP);          // template: A -> B (u64, seg 8)

    hist_rec_k<<<dim3(TILES, NSAMP), TPB>>>();                // samples pass-3 hist (u32 recs)
    hist_k<3><<<dim3(TILES, 1), TPB>>>(NSAMP);                // template pass-3 hist (u64)
    tscan_k<<<dim3(SEGS, 32), 256>>>(3);
    scatter_k<3, 2><<<dim3(TILES, 1), TPB>>>(NSAMP);          // template: B -> g_tval
    scatter_rec_k<<<dim3(TILES, NSAMP), TPB>>>(out);          // fused epilogue
}